// round 4
// baseline (speedup 1.0000x reference)
#include <cuda_runtime.h>
#include <cstdint>

#define T_DIM 1024
#define B_DIM 32
#define D_DIM 512
#define C_DIM 1024
#define BLANK 0

// Output packing (floats): [out (T*B*D)] [out_padding (B*T)] [gloss (B*T)] [new_len (B)]
#define OFF_PAD   ((size_t)T_DIM * B_DIM * D_DIM)
#define OFF_GLOSS (OFF_PAD + (size_t)B_DIM * T_DIM)
#define OFF_LEN   (OFF_GLOSS + (size_t)B_DIM * T_DIM)

// Scratch (device globals; no allocations allowed)
__device__ int g_pred[B_DIM * T_DIM];       // pred per (b,t), blank-forced by padding
__device__ int g_comp_t[B_DIM * T_DIM];     // original frame index of j-th non-blank frame
__device__ int g_run_start[B_DIM * T_DIM];  // compacted index of first frame of run n
__device__ int g_run_cnt[B_DIM * T_DIM];    // frames in run n
__device__ int g_new_len[B_DIM];            // number of runs per batch

// ---------------------------------------------------------------------------
// K1: argmax over C for each (t,b) row of logit [T,B,C]. Warp per row.
// ---------------------------------------------------------------------------
__global__ void argmax_kernel(const float* __restrict__ logit,
                              const unsigned char* __restrict__ padding) {
    int warp = (blockIdx.x * blockDim.x + threadIdx.x) >> 5;
    int lane = threadIdx.x & 31;
    if (warp >= T_DIM * B_DIM) return;
    int t = warp / B_DIM;
    int b = warp % B_DIM;

    const float4* row = reinterpret_cast<const float4*>(logit + (size_t)warp * C_DIM);

    float best = -3.402823466e+38f;
    int bi = 0;
    #pragma unroll
    for (int k = 0; k < C_DIM / (32 * 4); k++) {
        int i4 = lane + 32 * k;
        float4 v = row[i4];
        int base = i4 * 4;
        if (v.x > best) { best = v.x; bi = base; }
        if (v.y > best) { best = v.y; bi = base + 1; }
        if (v.z > best) { best = v.z; bi = base + 2; }
        if (v.w > best) { best = v.w; bi = base + 3; }
    }
    // warp reduce: strictly-greater wins; on exact tie, lower index wins
    #pragma unroll
    for (int off = 16; off; off >>= 1) {
        float ov = __shfl_down_sync(0xFFFFFFFFu, best, off);
        int   oi = __shfl_down_sync(0xFFFFFFFFu, bi, off);
        if (ov > best || (ov == best && oi < bi)) { best = ov; bi = oi; }
    }
    if (lane == 0) {
        int p = padding[b * T_DIM + t] ? BLANK : bi;
        g_pred[b * T_DIM + t] = p;
    }
}

// ---------------------------------------------------------------------------
// K2: per-batch compaction + run-length grouping. One block of T threads per b.
// Two-level scans (warp shfl + single cross-warp scan) -> only 6 barriers.
// ---------------------------------------------------------------------------
__global__ void rle_kernel(float* __restrict__ out) {
    int b = blockIdx.x;
    int t = threadIdx.x;           // 0..1023
    int lane = t & 31;
    int w = t >> 5;                // warp 0..31

    __shared__ int s_cp[T_DIM];
    __shared__ int s_runstart[T_DIM];
    __shared__ int s_w[32];

    int p = g_pred[b * T_DIM + t];
    int m = (p != BLANK) ? 1 : 0;

    // ---- scan 1: compaction destinations ----
    int v = m;
    #pragma unroll
    for (int o = 1; o < 32; o <<= 1) {
        int x = __shfl_up_sync(0xFFFFFFFFu, v, o);
        if (lane >= o) v += x;
    }
    if (lane == 31) s_w[w] = v;
    s_cp[t] = -1;                  // init compacted stream (pre-barrier)
    __syncthreads();               // (1)
    if (w == 0) {
        int x = s_w[lane];
        #pragma unroll
        for (int o = 1; o < 32; o <<= 1) {
            int y = __shfl_up_sync(0xFFFFFFFFu, x, o);
            if (lane >= o) x += y;
        }
        s_w[lane] = x;
    }
    __syncthreads();               // (2)
    int incl = v + (w ? s_w[w - 1] : 0);
    int nb_total = s_w[31];
    int dest = incl - 1;
    __syncthreads();               // (3) all reads of s_w / s_cp-init done before scatter

    if (m) {
        s_cp[dest] = p;
        g_comp_t[b * T_DIM + dest] = t;
    }
    __syncthreads();               // (4)

    // ---- scan 2: run starts on compacted stream ----
    int cj = s_cp[t];
    int prev = (t == 0) ? -2 : s_cp[t - 1];
    int st = (cj >= 0 && cj != prev) ? 1 : 0;

    v = st;
    #pragma unroll
    for (int o = 1; o < 32; o <<= 1) {
        int x = __shfl_up_sync(0xFFFFFFFFu, v, o);
        if (lane >= o) v += x;
    }
    if (lane == 31) s_w[w] = v;
    __syncthreads();               // (5)
    if (w == 0) {
        int x = s_w[lane];
        #pragma unroll
        for (int o = 1; o < 32; o <<= 1) {
            int y = __shfl_up_sync(0xFFFFFFFFu, x, o);
            if (lane >= o) x += y;
        }
        s_w[lane] = x;
    }
    __syncthreads();               // (6)
    int seg = v + (w ? s_w[w - 1] : 0) - 1;
    int new_len = s_w[31];

    if (st) s_runstart[seg] = t;
    __syncthreads();               // (7)

    // ---- per-run outputs (thread t = output position n) ----
    int n = t;
    float gloss = -1.0f;
    if (n < new_len) {
        int rs = s_runstart[n];
        int re = (n + 1 < new_len) ? s_runstart[n + 1] : nb_total;
        g_run_start[b * T_DIM + n] = rs;
        g_run_cnt[b * T_DIM + n] = re - rs;
        gloss = (float)s_cp[rs];
    }
    out[OFF_GLOSS + (size_t)b * T_DIM + n] = gloss;
    out[OFF_PAD   + (size_t)b * T_DIM + n] = (n >= new_len) ? 1.0f : 0.0f;
    if (t == 0) {
        g_new_len[b] = new_len;
        out[OFF_LEN + b] = (float)new_len;
    }
}

// ---------------------------------------------------------------------------
// K3: out[n,b,:] = mean of rep[t,b,:] over frames of run n; zeros if n>=len.
// Block per (n,b); 128 threads x float4 cover D=512.
// ---------------------------------------------------------------------------
__global__ void gather_avg_kernel(const float* __restrict__ rep,
                                  float* __restrict__ out) {
    int n = blockIdx.x;
    int b = blockIdx.y;
    int d4 = threadIdx.x;  // 0..127

    float4* orow = reinterpret_cast<float4*>(out + ((size_t)n * B_DIM + b) * D_DIM);
    int len = g_new_len[b];
    if (n >= len) {
        orow[d4] = make_float4(0.f, 0.f, 0.f, 0.f);
        return;
    }
    int rs  = g_run_start[b * T_DIM + n];
    int cnt = g_run_cnt[b * T_DIM + n];

    float4 acc = make_float4(0.f, 0.f, 0.f, 0.f);
    for (int k = 0; k < cnt; k++) {
        int t = g_comp_t[b * T_DIM + rs + k];
        const float4* rrow =
            reinterpret_cast<const float4*>(rep + ((size_t)t * B_DIM + b) * D_DIM);
        float4 v = rrow[d4];
        acc.x += v.x; acc.y += v.y; acc.z += v.z; acc.w += v.w;
    }
    float inv = 1.0f / (float)cnt;
    acc.x *= inv; acc.y *= inv; acc.z *= inv; acc.w *= inv;
    orow[d4] = acc;
}

extern "C" void kernel_launch(void* const* d_in, const int* in_sizes, int n_in,
                              void* d_out, int out_size) {
    const float* rep = (const float*)d_in[0];          // [T,B,D] f32
    const float* logit = (const float*)d_in[1];        // [T,B,C] f32
    const unsigned char* padding = (const unsigned char*)d_in[2];  // [B,T] bool
    float* out = (float*)d_out;

    // K1: 32768 rows, warp per row, 256 threads/block -> 8 rows/block
    argmax_kernel<<<(T_DIM * B_DIM) / 8, 256>>>(logit, padding);

    // K2: one block per batch
    rle_kernel<<<B_DIM, T_DIM>>>(out);

    // K3: block per (n,b)
    dim3 grid3(T_DIM, B_DIM);
    gather_avg_kernel<<<grid3, 128>>>(rep, out);
}

// round 6
// speedup vs baseline: 1.2808x; 1.2808x over previous
#include <cuda_runtime.h>
#include <cstdint>

#define T_DIM 1024
#define B_DIM 32
#define D_DIM 512
#define C_DIM 1024
#define BLANK 0

// Output packing (floats): [out (T*B*D)] [out_padding (B*T)] [gloss (B*T)] [new_len (B)]
#define OFF_PAD   ((size_t)T_DIM * B_DIM * D_DIM)
#define OFF_GLOSS (OFF_PAD + (size_t)B_DIM * T_DIM)
#define OFF_LEN   (OFF_GLOSS + (size_t)B_DIM * T_DIM)

// Scratch (device globals; no allocations allowed)
__device__ int g_pred[B_DIM * T_DIM];       // pred per (b,t), blank-forced by padding
__device__ int g_comp_t[B_DIM * T_DIM];     // original frame index of j-th non-blank frame
__device__ int g_run_start[B_DIM * T_DIM];  // compacted index of first frame of run n
__device__ int g_run_cnt[B_DIM * T_DIM];    // frames in run n
__device__ int g_new_len[B_DIM];            // number of runs per batch

// ---------------------------------------------------------------------------
// K1: argmax over C for each (t,b) row of logit [T,B,C]. Warp per row.
// ---------------------------------------------------------------------------
__global__ void argmax_kernel(const float* __restrict__ logit,
                              const unsigned char* __restrict__ padding) {
    int warp = (blockIdx.x * blockDim.x + threadIdx.x) >> 5;
    int lane = threadIdx.x & 31;
    if (warp >= T_DIM * B_DIM) return;
    int t = warp / B_DIM;
    int b = warp % B_DIM;

    const float4* row = reinterpret_cast<const float4*>(logit + (size_t)warp * C_DIM);

    float best = -3.402823466e+38f;
    int bi = 0;
    #pragma unroll
    for (int k = 0; k < C_DIM / (32 * 4); k++) {
        int i4 = lane + 32 * k;
        float4 v = row[i4];
        int base = i4 * 4;
        if (v.x > best) { best = v.x; bi = base; }
        if (v.y > best) { best = v.y; bi = base + 1; }
        if (v.z > best) { best = v.z; bi = base + 2; }
        if (v.w > best) { best = v.w; bi = base + 3; }
    }
    // warp reduce: strictly-greater wins; on exact tie, lower index wins
    #pragma unroll
    for (int off = 16; off; off >>= 1) {
        float ov = __shfl_down_sync(0xFFFFFFFFu, best, off);
        int   oi = __shfl_down_sync(0xFFFFFFFFu, bi, off);
        if (ov > best || (ov == best && oi < bi)) { best = ov; bi = oi; }
    }
    if (lane == 0) {
        int p = padding[b * T_DIM + t] ? BLANK : bi;
        g_pred[b * T_DIM + t] = p;
    }
}

// ---------------------------------------------------------------------------
// K2: per-batch compaction + run-length grouping. One block of T threads per b.
// Two-level scans (warp shfl + single cross-warp scan).
// ---------------------------------------------------------------------------
__global__ void rle_kernel(float* __restrict__ out) {
    int b = blockIdx.x;
    int t = threadIdx.x;           // 0..1023
    int lane = t & 31;
    int w = t >> 5;                // warp 0..31

    __shared__ int s_cp[T_DIM];
    __shared__ int s_runstart[T_DIM];
    __shared__ int s_w[32];

    int p = g_pred[b * T_DIM + t];
    int m = (p != BLANK) ? 1 : 0;

    // ---- scan 1: compaction destinations ----
    int v = m;
    #pragma unroll
    for (int o = 1; o < 32; o <<= 1) {
        int x = __shfl_up_sync(0xFFFFFFFFu, v, o);
        if (lane >= o) v += x;
    }
    if (lane == 31) s_w[w] = v;
    s_cp[t] = -1;                  // init compacted stream (pre-barrier)
    __syncthreads();               // (1)
    if (w == 0) {
        int x = s_w[lane];
        #pragma unroll
        for (int o = 1; o < 32; o <<= 1) {
            int y = __shfl_up_sync(0xFFFFFFFFu, x, o);
            if (lane >= o) x += y;
        }
        s_w[lane] = x;
    }
    __syncthreads();               // (2)
    int incl = v + (w ? s_w[w - 1] : 0);
    int nb_total = s_w[31];
    int dest = incl - 1;
    __syncthreads();               // (3)

    if (m) {
        s_cp[dest] = p;
        g_comp_t[b * T_DIM + dest] = t;
    }
    __syncthreads();               // (4)

    // ---- scan 2: run starts on compacted stream ----
    int cj = s_cp[t];
    int prev = (t == 0) ? -2 : s_cp[t - 1];
    int st = (cj >= 0 && cj != prev) ? 1 : 0;

    v = st;
    #pragma unroll
    for (int o = 1; o < 32; o <<= 1) {
        int x = __shfl_up_sync(0xFFFFFFFFu, v, o);
        if (lane >= o) v += x;
    }
    if (lane == 31) s_w[w] = v;
    __syncthreads();               // (5)
    if (w == 0) {
        int x = s_w[lane];
        #pragma unroll
        for (int o = 1; o < 32; o <<= 1) {
            int y = __shfl_up_sync(0xFFFFFFFFu, x, o);
            if (lane >= o) x += y;
        }
        s_w[lane] = x;
    }
    __syncthreads();               // (6)
    int seg = v + (w ? s_w[w - 1] : 0) - 1;
    int new_len = s_w[31];

    if (st) s_runstart[seg] = t;
    __syncthreads();               // (7)

    // ---- per-run outputs (thread t = output position n) ----
    int n = t;
    float gloss = -1.0f;
    if (n < new_len) {
        int rs = s_runstart[n];
        int re = (n + 1 < new_len) ? s_runstart[n + 1] : nb_total;
        g_run_start[b * T_DIM + n] = rs;
        g_run_cnt[b * T_DIM + n] = re - rs;
        gloss = (float)s_cp[rs];
    }
    out[OFF_GLOSS + (size_t)b * T_DIM + n] = gloss;
    out[OFF_PAD   + (size_t)b * T_DIM + n] = (n >= new_len) ? 1.0f : 0.0f;
    if (t == 0) {
        g_new_len[b] = new_len;
        out[OFF_LEN + b] = (float)new_len;
    }
}

// ---------------------------------------------------------------------------
// K3v2: warp per output row (n,b); each lane owns 4 float4 chunks (stride 32)
// -> 4 independent LDG.128 in flight per lane per frame. 8 rows per 256-thread
// block amortizes the metadata-chain latency.
// ---------------------------------------------------------------------------
__global__ void gather_avg_kernel(const float* __restrict__ rep,
                                  float* __restrict__ out) {
    int b = blockIdx.y;
    int warp_in_blk = threadIdx.x >> 5;
    int lane = threadIdx.x & 31;
    int n = blockIdx.x * 8 + warp_in_blk;   // output row

    float4* orow = reinterpret_cast<float4*>(out + ((size_t)n * B_DIM + b) * D_DIM);
    int len = g_new_len[b];

    if (n >= len) {
        float4 z = make_float4(0.f, 0.f, 0.f, 0.f);
        #pragma unroll
        for (int j = 0; j < 4; j++) orow[lane + 32 * j] = z;
        return;
    }

    int rs  = g_run_start[b * T_DIM + n];
    int cnt = g_run_cnt[b * T_DIM + n];
    const int* ct = g_comp_t + b * T_DIM + rs;

    float4 acc0 = make_float4(0.f, 0.f, 0.f, 0.f);
    float4 acc1 = acc0, acc2 = acc0, acc3 = acc0;

    for (int k = 0; k < cnt; k++) {
        int t = ct[k];   // broadcast load
        const float4* rrow =
            reinterpret_cast<const float4*>(rep + ((size_t)t * B_DIM + b) * D_DIM);
        float4 v0 = rrow[lane];
        float4 v1 = rrow[lane + 32];
        float4 v2 = rrow[lane + 64];
        float4 v3 = rrow[lane + 96];
        acc0.x += v0.x; acc0.y += v0.y; acc0.z += v0.z; acc0.w += v0.w;
        acc1.x += v1.x; acc1.y += v1.y; acc1.z += v1.z; acc1.w += v1.w;
        acc2.x += v2.x; acc2.y += v2.y; acc2.z += v2.z; acc2.w += v2.w;
        acc3.x += v3.x; acc3.y += v3.y; acc3.z += v3.z; acc3.w += v3.w;
    }
    float inv = 1.0f / (float)cnt;
    acc0.x *= inv; acc0.y *= inv; acc0.z *= inv; acc0.w *= inv;
    acc1.x *= inv; acc1.y *= inv; acc1.z *= inv; acc1.w *= inv;
    acc2.x *= inv; acc2.y *= inv; acc2.z *= inv; acc2.w *= inv;
    acc3.x *= inv; acc3.y *= inv; acc3.z *= inv; acc3.w *= inv;
    orow[lane]      = acc0;
    orow[lane + 32] = acc1;
    orow[lane + 64] = acc2;
    orow[lane + 96] = acc3;
}

extern "C" void kernel_launch(void* const* d_in, const int* in_sizes, int n_in,
                              void* d_out, int out_size) {
    const float* rep = (const float*)d_in[0];          // [T,B,D] f32
    const float* logit = (const float*)d_in[1];        // [T,B,C] f32
    const unsigned char* padding = (const unsigned char*)d_in[2];  // [B,T] bool
    float* out = (float*)d_out;

    // K1: 32768 rows, warp per row, 256 threads/block -> 8 rows/block
    argmax_kernel<<<(T_DIM * B_DIM) / 8, 256>>>(logit, padding);

    // K2: one block per batch
    rle_kernel<<<B_DIM, T_DIM>>>(out);

    // K3v2: warp per output row, 8 rows per block
    dim3 grid3(T_DIM / 8, B_DIM);
    gather_avg_kernel<<<grid3, 256>>>(rep, out);
}

// round 7
// speedup vs baseline: 1.2883x; 1.0059x over previous
#include <cuda_runtime.h>
#include <cstdint>

#define T_DIM 1024
#define B_DIM 32
#define D_DIM 512
#define C_DIM 1024
#define BLANK 0

// Output packing (floats): [out (T*B*D)] [out_padding (B*T)] [gloss (B*T)] [new_len (B)]
#define OFF_PAD   ((size_t)T_DIM * B_DIM * D_DIM)
#define OFF_GLOSS (OFF_PAD + (size_t)B_DIM * T_DIM)
#define OFF_LEN   (OFF_GLOSS + (size_t)B_DIM * T_DIM)

// Scratch (device globals; no allocations allowed)
__device__ int g_pred[B_DIM * T_DIM];       // pred per (b,t), blank-forced by padding
__device__ int g_comp_t[B_DIM * T_DIM];     // original frame index of j-th non-blank frame
__device__ int g_run_start[B_DIM * T_DIM];  // compacted index of first frame of run n
__device__ int g_run_cnt[B_DIM * T_DIM];    // frames in run n
__device__ int g_new_len[B_DIM];            // number of runs per batch

// ---------------------------------------------------------------------------
// K1: argmax over C for each (t,b) row of logit [T,B,C]. Warp per row.
// ---------------------------------------------------------------------------
__global__ void argmax_kernel(const float* __restrict__ logit,
                              const unsigned char* __restrict__ padding) {
    int warp = (blockIdx.x * blockDim.x + threadIdx.x) >> 5;
    int lane = threadIdx.x & 31;
    if (warp >= T_DIM * B_DIM) return;
    int t = warp / B_DIM;
    int b = warp % B_DIM;

    const float4* row = reinterpret_cast<const float4*>(logit + (size_t)warp * C_DIM);

    float best = -3.402823466e+38f;
    int bi = 0;
    #pragma unroll
    for (int k = 0; k < C_DIM / (32 * 4); k++) {
        int i4 = lane + 32 * k;
        float4 v = row[i4];
        int base = i4 * 4;
        if (v.x > best) { best = v.x; bi = base; }
        if (v.y > best) { best = v.y; bi = base + 1; }
        if (v.z > best) { best = v.z; bi = base + 2; }
        if (v.w > best) { best = v.w; bi = base + 3; }
    }
    // warp reduce: strictly-greater wins; on exact tie, lower index wins
    #pragma unroll
    for (int off = 16; off; off >>= 1) {
        float ov = __shfl_down_sync(0xFFFFFFFFu, best, off);
        int   oi = __shfl_down_sync(0xFFFFFFFFu, bi, off);
        if (ov > best || (ov == best && oi < bi)) { best = ov; bi = oi; }
    }
    if (lane == 0) {
        int p = padding[b * T_DIM + t] ? BLANK : bi;
        g_pred[b * T_DIM + t] = p;
    }
}

// ---------------------------------------------------------------------------
// K2: per-batch compaction + run-length grouping. One block of T threads per b.
// Two-level scans (warp shfl + single cross-warp scan).
// ---------------------------------------------------------------------------
__global__ void rle_kernel(float* __restrict__ out) {
    int b = blockIdx.x;
    int t = threadIdx.x;           // 0..1023
    int lane = t & 31;
    int w = t >> 5;                // warp 0..31

    __shared__ int s_cp[T_DIM];
    __shared__ int s_runstart[T_DIM];
    __shared__ int s_w[32];

    int p = g_pred[b * T_DIM + t];
    int m = (p != BLANK) ? 1 : 0;

    // ---- scan 1: compaction destinations ----
    int v = m;
    #pragma unroll
    for (int o = 1; o < 32; o <<= 1) {
        int x = __shfl_up_sync(0xFFFFFFFFu, v, o);
        if (lane >= o) v += x;
    }
    if (lane == 31) s_w[w] = v;
    s_cp[t] = -1;                  // init compacted stream (pre-barrier)
    __syncthreads();               // (1)
    if (w == 0) {
        int x = s_w[lane];
        #pragma unroll
        for (int o = 1; o < 32; o <<= 1) {
            int y = __shfl_up_sync(0xFFFFFFFFu, x, o);
            if (lane >= o) x += y;
        }
        s_w[lane] = x;
    }
    __syncthreads();               // (2)
    int incl = v + (w ? s_w[w - 1] : 0);
    int nb_total = s_w[31];
    int dest = incl - 1;
    __syncthreads();               // (3)

    if (m) {
        s_cp[dest] = p;
        g_comp_t[b * T_DIM + dest] = t;
    }
    __syncthreads();               // (4)

    // ---- scan 2: run starts on compacted stream ----
    int cj = s_cp[t];
    int prev = (t == 0) ? -2 : s_cp[t - 1];
    int st = (cj >= 0 && cj != prev) ? 1 : 0;

    v = st;
    #pragma unroll
    for (int o = 1; o < 32; o <<= 1) {
        int x = __shfl_up_sync(0xFFFFFFFFu, v, o);
        if (lane >= o) v += x;
    }
    if (lane == 31) s_w[w] = v;
    __syncthreads();               // (5)
    if (w == 0) {
        int x = s_w[lane];
        #pragma unroll
        for (int o = 1; o < 32; o <<= 1) {
            int y = __shfl_up_sync(0xFFFFFFFFu, x, o);
            if (lane >= o) x += y;
        }
        s_w[lane] = x;
    }
    __syncthreads();               // (6)
    int seg = v + (w ? s_w[w - 1] : 0) - 1;
    int new_len = s_w[31];

    if (st) s_runstart[seg] = t;
    __syncthreads();               // (7)

    // ---- per-run outputs (thread t = output position n) ----
    int n = t;
    float gloss = -1.0f;
    if (n < new_len) {
        int rs = s_runstart[n];
        int re = (n + 1 < new_len) ? s_runstart[n + 1] : nb_total;
        g_run_start[b * T_DIM + n] = rs;
        g_run_cnt[b * T_DIM + n] = re - rs;
        gloss = (float)s_cp[rs];
    }
    out[OFF_GLOSS + (size_t)b * T_DIM + n] = gloss;
    out[OFF_PAD   + (size_t)b * T_DIM + n] = (n >= new_len) ? 1.0f : 0.0f;
    if (t == 0) {
        g_new_len[b] = new_len;
        out[OFF_LEN + b] = (float)new_len;
    }
}

// ---------------------------------------------------------------------------
// K3v2: warp per output row (n,b); each lane owns 4 float4 chunks (stride 32)
// -> 4 independent LDG.128 in flight per lane per frame. 8 rows per 256-thread
// block amortizes the metadata-chain latency.
// ---------------------------------------------------------------------------
__global__ void gather_avg_kernel(const float* __restrict__ rep,
                                  float* __restrict__ out) {
    int b = blockIdx.y;
    int warp_in_blk = threadIdx.x >> 5;
    int lane = threadIdx.x & 31;
    int n = blockIdx.x * 8 + warp_in_blk;   // output row

    float4* orow = reinterpret_cast<float4*>(out + ((size_t)n * B_DIM + b) * D_DIM);
    int len = g_new_len[b];

    if (n >= len) {
        float4 z = make_float4(0.f, 0.f, 0.f, 0.f);
        #pragma unroll
        for (int j = 0; j < 4; j++) orow[lane + 32 * j] = z;
        return;
    }

    int rs  = g_run_start[b * T_DIM + n];
    int cnt = g_run_cnt[b * T_DIM + n];
    const int* ct = g_comp_t + b * T_DIM + rs;

    float4 acc0 = make_float4(0.f, 0.f, 0.f, 0.f);
    float4 acc1 = acc0, acc2 = acc0, acc3 = acc0;

    for (int k = 0; k < cnt; k++) {
        int t = ct[k];   // broadcast load
        const float4* rrow =
            reinterpret_cast<const float4*>(rep + ((size_t)t * B_DIM + b) * D_DIM);
        float4 v0 = rrow[lane];
        float4 v1 = rrow[lane + 32];
        float4 v2 = rrow[lane + 64];
        float4 v3 = rrow[lane + 96];
        acc0.x += v0.x; acc0.y += v0.y; acc0.z += v0.z; acc0.w += v0.w;
        acc1.x += v1.x; acc1.y += v1.y; acc1.z += v1.z; acc1.w += v1.w;
        acc2.x += v2.x; acc2.y += v2.y; acc2.z += v2.z; acc2.w += v2.w;
        acc3.x += v3.x; acc3.y += v3.y; acc3.z += v3.z; acc3.w += v3.w;
    }
    float inv = 1.0f / (float)cnt;
    acc0.x *= inv; acc0.y *= inv; acc0.z *= inv; acc0.w *= inv;
    acc1.x *= inv; acc1.y *= inv; acc1.z *= inv; acc1.w *= inv;
    acc2.x *= inv; acc2.y *= inv; acc2.z *= inv; acc2.w *= inv;
    acc3.x *= inv; acc3.y *= inv; acc3.z *= inv; acc3.w *= inv;
    orow[lane]      = acc0;
    orow[lane + 32] = acc1;
    orow[lane + 64] = acc2;
    orow[lane + 96] = acc3;
}

extern "C" void kernel_launch(void* const* d_in, const int* in_sizes, int n_in,
                              void* d_out, int out_size) {
    const float* rep = (const float*)d_in[0];          // [T,B,D] f32
    const float* logit = (const float*)d_in[1];        // [T,B,C] f32
    const unsigned char* padding = (const unsigned char*)d_in[2];  // [B,T] bool
    float* out = (float*)d_out;

    // K1: 32768 rows, warp per row, 256 threads/block -> 8 rows/block
    argmax_kernel<<<(T_DIM * B_DIM) / 8, 256>>>(logit, padding);

    // K2: one block per batch
    rle_kernel<<<B_DIM, T_DIM>>>(out);

    // K3v2: warp per output row, 8 rows per block
    dim3 grid3(T_DIM / 8, B_DIM);
    gather_avg_kernel<<<grid3, 256>>>(rep, out);
}

// round 8
// speedup vs baseline: 1.3366x; 1.0375x over previous
#include <cuda_runtime.h>
#include <cstdint>

#define T_DIM 1024
#define B_DIM 32
#define D_DIM 512
#define C_DIM 1024
#define BLANK 0

// Output packing (floats): [out (T*B*D)] [out_padding (B*T)] [gloss (B*T)] [new_len (B)]
#define OFF_PAD   ((size_t)T_DIM * B_DIM * D_DIM)
#define OFF_GLOSS (OFF_PAD + (size_t)B_DIM * T_DIM)
#define OFF_LEN   (OFF_GLOSS + (size_t)B_DIM * T_DIM)

// Scratch (device globals; no allocations allowed)
__device__ int g_pred[B_DIM * T_DIM];       // pred per (b,t), blank-forced by padding
__device__ int g_comp_t[B_DIM * T_DIM];     // original frame index of j-th non-blank frame
__device__ int g_run_start[B_DIM * T_DIM];  // compacted index of first frame of run n
__device__ int g_run_cnt[B_DIM * T_DIM];    // frames in run n
__device__ int g_new_len[B_DIM];            // number of runs per batch

// ---------------------------------------------------------------------------
// K1: argmax over C for each (t,b) row of logit [T,B,C]. Warp per row.
// v2: all 8 float4 loaded into regs FIRST (forces MLP=8), then a short
// max-tree reduce (quad-local tree + 8-step chain) instead of a 32-op chain.
// ---------------------------------------------------------------------------
__global__ void argmax_kernel(const float* __restrict__ logit,
                              const unsigned char* __restrict__ padding) {
    int warp = (blockIdx.x * blockDim.x + threadIdx.x) >> 5;
    int lane = threadIdx.x & 31;
    if (warp >= T_DIM * B_DIM) return;
    int t = warp / B_DIM;
    int b = warp % B_DIM;

    const float4* row = reinterpret_cast<const float4*>(logit + (size_t)warp * C_DIM);

    // Batch all loads up front: 8 independent LDG.128 in flight.
    float4 v[8];
    #pragma unroll
    for (int k = 0; k < 8; k++) v[k] = row[lane + 32 * k];

    // Reduce. Lowest index wins on ties everywhere:
    //  - within quad: only replace on strictly-greater (x<y<z<w index order)
    //  - across quads (ascending k => ascending index): strictly-greater
    float best = -3.402823466e+38f;
    int bi = 0;
    #pragma unroll
    for (int k = 0; k < 8; k++) {
        int base = (lane + 32 * k) * 4;
        float m01 = v[k].x; int i01 = base;
        if (v[k].y > m01) { m01 = v[k].y; i01 = base + 1; }
        float m23 = v[k].z; int i23 = base + 2;
        if (v[k].w > m23) { m23 = v[k].w; i23 = base + 3; }
        float mq = m01; int iq = i01;
        if (m23 > mq) { mq = m23; iq = i23; }
        if (mq > best) { best = mq; bi = iq; }
    }
    // warp reduce: strictly-greater wins; on exact tie, lower index wins
    #pragma unroll
    for (int off = 16; off; off >>= 1) {
        float ov = __shfl_down_sync(0xFFFFFFFFu, best, off);
        int   oi = __shfl_down_sync(0xFFFFFFFFu, bi, off);
        if (ov > best || (ov == best && oi < bi)) { best = ov; bi = oi; }
    }
    if (lane == 0) {
        int p = padding[b * T_DIM + t] ? BLANK : bi;
        g_pred[b * T_DIM + t] = p;
    }
}

// ---------------------------------------------------------------------------
// K2: per-batch compaction + run-length grouping. One block of T threads per b.
// Two-level scans (warp shfl + single cross-warp scan).
// ---------------------------------------------------------------------------
__global__ void rle_kernel(float* __restrict__ out) {
    int b = blockIdx.x;
    int t = threadIdx.x;           // 0..1023
    int lane = t & 31;
    int w = t >> 5;                // warp 0..31

    __shared__ int s_cp[T_DIM];
    __shared__ int s_runstart[T_DIM];
    __shared__ int s_w[32];

    int p = g_pred[b * T_DIM + t];
    int m = (p != BLANK) ? 1 : 0;

    // ---- scan 1: compaction destinations ----
    int v = m;
    #pragma unroll
    for (int o = 1; o < 32; o <<= 1) {
        int x = __shfl_up_sync(0xFFFFFFFFu, v, o);
        if (lane >= o) v += x;
    }
    if (lane == 31) s_w[w] = v;
    s_cp[t] = -1;                  // init compacted stream (pre-barrier)
    __syncthreads();               // (1)
    if (w == 0) {
        int x = s_w[lane];
        #pragma unroll
        for (int o = 1; o < 32; o <<= 1) {
            int y = __shfl_up_sync(0xFFFFFFFFu, x, o);
            if (lane >= o) x += y;
        }
        s_w[lane] = x;
    }
    __syncthreads();               // (2)
    int incl = v + (w ? s_w[w - 1] : 0);
    int nb_total = s_w[31];
    int dest = incl - 1;
    __syncthreads();               // (3)

    if (m) {
        s_cp[dest] = p;
        g_comp_t[b * T_DIM + dest] = t;
    }
    __syncthreads();               // (4)

    // ---- scan 2: run starts on compacted stream ----
    int cj = s_cp[t];
    int prev = (t == 0) ? -2 : s_cp[t - 1];
    int st = (cj >= 0 && cj != prev) ? 1 : 0;

    v = st;
    #pragma unroll
    for (int o = 1; o < 32; o <<= 1) {
        int x = __shfl_up_sync(0xFFFFFFFFu, v, o);
        if (lane >= o) v += x;
    }
    if (lane == 31) s_w[w] = v;
    __syncthreads();               // (5)
    if (w == 0) {
        int x = s_w[lane];
        #pragma unroll
        for (int o = 1; o < 32; o <<= 1) {
            int y = __shfl_up_sync(0xFFFFFFFFu, x, o);
            if (lane >= o) x += y;
        }
        s_w[lane] = x;
    }
    __syncthreads();               // (6)
    int seg = v + (w ? s_w[w - 1] : 0) - 1;
    int new_len = s_w[31];

    if (st) s_runstart[seg] = t;
    __syncthreads();               // (7)

    // ---- per-run outputs (thread t = output position n) ----
    int n = t;
    float gloss = -1.0f;
    if (n < new_len) {
        int rs = s_runstart[n];
        int re = (n + 1 < new_len) ? s_runstart[n + 1] : nb_total;
        g_run_start[b * T_DIM + n] = rs;
        g_run_cnt[b * T_DIM + n] = re - rs;
        gloss = (float)s_cp[rs];
    }
    out[OFF_GLOSS + (size_t)b * T_DIM + n] = gloss;
    out[OFF_PAD   + (size_t)b * T_DIM + n] = (n >= new_len) ? 1.0f : 0.0f;
    if (t == 0) {
        g_new_len[b] = new_len;
        out[OFF_LEN + b] = (float)new_len;
    }
}

// ---------------------------------------------------------------------------
// K3v3: warp handles TWO output rows (n, n+512) of batch b. Fast path when
// every valid row has cnt==1 (the overwhelmingly common case: labels are
// i.i.d., runs rarely repeat): output row is a pure copy of one rep row, and
// we issue all 8 independent LDG.128 before any store (MLP=8). Fallback:
// sequential per-row averaging loop.
// ---------------------------------------------------------------------------
__global__ void gather_avg_kernel(const float* __restrict__ rep,
                                  float* __restrict__ out) {
    int b = blockIdx.y;
    int warp_in_blk = threadIdx.x >> 5;
    int lane = threadIdx.x & 31;
    int n0 = blockIdx.x * 8 + warp_in_blk;   // 0..511
    int n1 = n0 + (T_DIM / 2);               // 512..1023

    int len = g_new_len[b];
    float4* o0 = reinterpret_cast<float4*>(out + ((size_t)n0 * B_DIM + b) * D_DIM);
    float4* o1 = reinterpret_cast<float4*>(out + ((size_t)n1 * B_DIM + b) * D_DIM);

    bool v0 = n0 < len;
    bool v1 = n1 < len;
    int rs0 = 0, c0 = 1, rs1 = 0, c1 = 1;
    if (v0) { rs0 = g_run_start[b * T_DIM + n0]; c0 = g_run_cnt[b * T_DIM + n0]; }
    if (v1) { rs1 = g_run_start[b * T_DIM + n1]; c1 = g_run_cnt[b * T_DIM + n1]; }

    float4 z = make_float4(0.f, 0.f, 0.f, 0.f);

    if ((!v0 || c0 == 1) && (!v1 || c1 == 1)) {
        // Fast path: each valid row is a copy of exactly one rep row.
        const float4* r0 = nullptr;
        const float4* r1 = nullptr;
        if (v0) {
            int t0 = g_comp_t[b * T_DIM + rs0];
            r0 = reinterpret_cast<const float4*>(rep + ((size_t)t0 * B_DIM + b) * D_DIM);
        }
        if (v1) {
            int t1 = g_comp_t[b * T_DIM + rs1];
            r1 = reinterpret_cast<const float4*>(rep + ((size_t)t1 * B_DIM + b) * D_DIM);
        }
        float4 a0 = z, a1 = z, a2 = z, a3 = z;
        float4 b0 = z, b1 = z, b2 = z, b3 = z;
        if (v0) { a0 = r0[lane]; a1 = r0[lane + 32]; a2 = r0[lane + 64]; a3 = r0[lane + 96]; }
        if (v1) { b0 = r1[lane]; b1 = r1[lane + 32]; b2 = r1[lane + 64]; b3 = r1[lane + 96]; }
        o0[lane]      = a0; o0[lane + 32] = a1; o0[lane + 64] = a2; o0[lane + 96] = a3;
        o1[lane]      = b0; o1[lane + 32] = b1; o1[lane + 64] = b2; o1[lane + 96] = b3;
        return;
    }

    // General path: per-row averaging loop.
    #pragma unroll
    for (int r = 0; r < 2; r++) {
        bool valid = r ? v1 : v0;
        int rs = r ? rs1 : rs0;
        int cnt = r ? c1 : c0;
        float4* orow = r ? o1 : o0;
        if (!valid) {
            orow[lane] = z; orow[lane + 32] = z; orow[lane + 64] = z; orow[lane + 96] = z;
            continue;
        }
        const int* ct = g_comp_t + b * T_DIM + rs;
        float4 acc0 = z, acc1 = z, acc2 = z, acc3 = z;
        for (int k = 0; k < cnt; k++) {
            int t = ct[k];
            const float4* rrow =
                reinterpret_cast<const float4*>(rep + ((size_t)t * B_DIM + b) * D_DIM);
            float4 q0 = rrow[lane];
            float4 q1 = rrow[lane + 32];
            float4 q2 = rrow[lane + 64];
            float4 q3 = rrow[lane + 96];
            acc0.x += q0.x; acc0.y += q0.y; acc0.z += q0.z; acc0.w += q0.w;
            acc1.x += q1.x; acc1.y += q1.y; acc1.z += q1.z; acc1.w += q1.w;
            acc2.x += q2.x; acc2.y += q2.y; acc2.z += q2.z; acc2.w += q2.w;
            acc3.x += q3.x; acc3.y += q3.y; acc3.z += q3.z; acc3.w += q3.w;
        }
        float inv = 1.0f / (float)cnt;
        acc0.x *= inv; acc0.y *= inv; acc0.z *= inv; acc0.w *= inv;
        acc1.x *= inv; acc1.y *= inv; acc1.z *= inv; acc1.w *= inv;
        acc2.x *= inv; acc2.y *= inv; acc2.z *= inv; acc2.w *= inv;
        acc3.x *= inv; acc3.y *= inv; acc3.z *= inv; acc3.w *= inv;
        orow[lane]      = acc0;
        orow[lane + 32] = acc1;
        orow[lane + 64] = acc2;
        orow[lane + 96] = acc3;
    }
}

extern "C" void kernel_launch(void* const* d_in, const int* in_sizes, int n_in,
                              void* d_out, int out_size) {
    const float* rep = (const float*)d_in[0];          // [T,B,D] f32
    const float* logit = (const float*)d_in[1];        // [T,B,C] f32
    const unsigned char* padding = (const unsigned char*)d_in[2];  // [B,T] bool
    float* out = (float*)d_out;

    // K1: 32768 rows, warp per row, 256 threads/block -> 8 rows/block
    argmax_kernel<<<(T_DIM * B_DIM) / 8, 256>>>(logit, padding);

    // K2: one block per batch
    rle_kernel<<<B_DIM, T_DIM>>>(out);

    // K3v3: warp per 2 output rows (n, n+512), 8 warp-pairs per block
    dim3 grid3(T_DIM / 2 / 8, B_DIM);
    gather_avg_kernel<<<grid3, 256>>>(rep, out);
}

// round 9
// speedup vs baseline: 1.3763x; 1.0297x over previous
#include <cuda_runtime.h>
#include <cstdint>

#define T_DIM 1024
#define B_DIM 32
#define D_DIM 512
#define C_DIM 1024
#define BLANK 0

// Output packing (floats): [out (T*B*D)] [out_padding (B*T)] [gloss (B*T)] [new_len (B)]
#define OFF_PAD   ((size_t)T_DIM * B_DIM * D_DIM)
#define OFF_GLOSS (OFF_PAD + (size_t)B_DIM * T_DIM)
#define OFF_LEN   (OFF_GLOSS + (size_t)B_DIM * T_DIM)

// Scratch (device global; no allocations allowed)
__device__ int g_pred[B_DIM * T_DIM];   // pred per (b,t), blank-forced by padding

// ---------------------------------------------------------------------------
// K1: argmax over C for each (t,b) row of logit [T,B,C]. Warp per row.
// ---------------------------------------------------------------------------
__global__ void argmax_kernel(const float* __restrict__ logit,
                              const unsigned char* __restrict__ padding) {
    int warp = (blockIdx.x * blockDim.x + threadIdx.x) >> 5;
    int lane = threadIdx.x & 31;
    if (warp >= T_DIM * B_DIM) return;
    int t = warp / B_DIM;
    int b = warp % B_DIM;

    const float4* row = reinterpret_cast<const float4*>(logit + (size_t)warp * C_DIM);

    float4 v[8];
    #pragma unroll
    for (int k = 0; k < 8; k++) v[k] = row[lane + 32 * k];

    // Lowest index wins on ties (strictly-greater replaces, ascending order).
    float best = -3.402823466e+38f;
    int bi = 0;
    #pragma unroll
    for (int k = 0; k < 8; k++) {
        int base = (lane + 32 * k) * 4;
        float m01 = v[k].x; int i01 = base;
        if (v[k].y > m01) { m01 = v[k].y; i01 = base + 1; }
        float m23 = v[k].z; int i23 = base + 2;
        if (v[k].w > m23) { m23 = v[k].w; i23 = base + 3; }
        float mq = m01; int iq = i01;
        if (m23 > mq) { mq = m23; iq = i23; }
        if (mq > best) { best = mq; bi = iq; }
    }
    #pragma unroll
    for (int off = 16; off; off >>= 1) {
        float ov = __shfl_down_sync(0xFFFFFFFFu, best, off);
        int   oi = __shfl_down_sync(0xFFFFFFFFu, bi, off);
        if (ov > best || (ov == best && oi < bi)) { best = ov; bi = oi; }
    }
    if (lane == 0) {
        int p = padding[b * T_DIM + t] ? BLANK : bi;
        g_pred[b * T_DIM + t] = p;
    }
}

// ---------------------------------------------------------------------------
// K23: fused RLE + gather/average. Grid (64, B). Every block redundantly
// computes its batch's run-length structure in shared memory (cheap: two
// two-level scans over 1024 elements, g_pred row is L2-resident), then
// 8 warps x 2 output rows each do the bandwidth work. blockIdx.x==0 blocks
// also emit the small outputs (gloss / padding / new_len).
// ---------------------------------------------------------------------------
__global__ void __launch_bounds__(256)
fused_rle_gather(const float* __restrict__ rep, float* __restrict__ out) {
    int b = blockIdx.y;
    int tid = threadIdx.x;         // 0..255
    int lane = tid & 31;
    int w = tid >> 5;              // warp 0..7

    __shared__ int s_cp[T_DIM];        // compacted predictions
    __shared__ int s_ct[T_DIM];        // compacted original frame index
    __shared__ int s_rs[T_DIM + 1];    // run start (compacted idx); s_rs[len]=nb_total
    __shared__ int s_w[8];
    __shared__ int s_w2[8];

    // ---- phase 1: load pred row, scan mask -> compaction ----
    int4 p4 = reinterpret_cast<const int4*>(g_pred + b * T_DIM)[tid];
    int m0 = p4.x != BLANK, m1 = p4.y != BLANK, m2 = p4.z != BLANK, m3 = p4.w != BLANK;
    int local = m0 + m1 + m2 + m3;

    int v = local;
    #pragma unroll
    for (int o = 1; o < 32; o <<= 1) {
        int x = __shfl_up_sync(0xFFFFFFFFu, v, o);
        if (lane >= o) v += x;
    }
    if (lane == 31) s_w[w] = v;
    reinterpret_cast<int4*>(s_cp)[tid] = make_int4(-1, -1, -1, -1);
    __syncthreads();
    if (tid == 0) {
        int run = 0;
        #pragma unroll
        for (int j = 0; j < 8; j++) { run += s_w[j]; s_w[j] = run; }
    }
    __syncthreads();
    int base = (w ? s_w[w - 1] : 0) + (v - local);   // exclusive start
    int nb_total = s_w[7];

    int d = base;
    if (m0) { s_cp[d] = p4.x; s_ct[d] = 4 * tid;     d++; }
    if (m1) { s_cp[d] = p4.y; s_ct[d] = 4 * tid + 1; d++; }
    if (m2) { s_cp[d] = p4.z; s_ct[d] = 4 * tid + 2; d++; }
    if (m3) { s_cp[d] = p4.w; s_ct[d] = 4 * tid + 3; d++; }
    __syncthreads();

    // ---- phase 2: run-start scan on compacted stream ----
    int i0 = 4 * tid;
    int c0 = s_cp[i0], c1 = s_cp[i0 + 1], c2 = s_cp[i0 + 2], c3 = s_cp[i0 + 3];
    int pm1 = (i0 == 0) ? -2 : s_cp[i0 - 1];
    int st0 = (c0 >= 0) && (c0 != pm1);
    int st1 = (c1 >= 0) && (c1 != c0);
    int st2 = (c2 >= 0) && (c2 != c1);
    int st3 = (c3 >= 0) && (c3 != c2);
    int local2 = st0 + st1 + st2 + st3;

    int v2 = local2;
    #pragma unroll
    for (int o = 1; o < 32; o <<= 1) {
        int x = __shfl_up_sync(0xFFFFFFFFu, v2, o);
        if (lane >= o) v2 += x;
    }
    if (lane == 31) s_w2[w] = v2;
    __syncthreads();
    if (tid == 0) {
        int run = 0;
        #pragma unroll
        for (int j = 0; j < 8; j++) { run += s_w2[j]; s_w2[j] = run; }
    }
    __syncthreads();
    int base2 = (w ? s_w2[w - 1] : 0) + (v2 - local2);
    int new_len = s_w2[7];

    int d2 = base2;
    if (st0) s_rs[d2++] = i0;
    if (st1) s_rs[d2++] = i0 + 1;
    if (st2) s_rs[d2++] = i0 + 2;
    if (st3) s_rs[d2++] = i0 + 3;
    if (tid == 0) s_rs[new_len] = nb_total;
    __syncthreads();

    // ---- small outputs (one block column only) ----
    if (blockIdx.x == 0) {
        #pragma unroll
        for (int j = 0; j < 4; j++) {
            int n = tid + 256 * j;
            float gloss = -1.0f;
            if (n < new_len) gloss = (float)s_cp[s_rs[n]];
            out[OFF_GLOSS + (size_t)b * T_DIM + n] = gloss;
            out[OFF_PAD   + (size_t)b * T_DIM + n] = (n >= new_len) ? 1.0f : 0.0f;
        }
        if (tid == 0) out[OFF_LEN + b] = (float)new_len;
    }

    // ---- phase 3: gather/average. Warp handles rows n0 and n0+512 ----
    int n0 = blockIdx.x * 8 + w;           // 0..511
    int n1 = n0 + (T_DIM / 2);             // 512..1023

    float4* o0 = reinterpret_cast<float4*>(out + ((size_t)n0 * B_DIM + b) * D_DIM);
    float4* o1 = reinterpret_cast<float4*>(out + ((size_t)n1 * B_DIM + b) * D_DIM);

    bool v0ok = n0 < new_len;
    bool v1ok = n1 < new_len;
    int rs0 = 0, cc0 = 1, rs1 = 0, cc1 = 1;
    if (v0ok) { rs0 = s_rs[n0]; cc0 = s_rs[n0 + 1] - rs0; }
    if (v1ok) { rs1 = s_rs[n1]; cc1 = s_rs[n1 + 1] - rs1; }

    float4 z = make_float4(0.f, 0.f, 0.f, 0.f);

    if ((!v0ok || cc0 == 1) && (!v1ok || cc1 == 1)) {
        // Fast path: each valid row is a pure copy of one rep row (MLP=8).
        const float4* r0 = nullptr;
        const float4* r1 = nullptr;
        if (v0ok) {
            int t0 = s_ct[rs0];
            r0 = reinterpret_cast<const float4*>(rep + ((size_t)t0 * B_DIM + b) * D_DIM);
        }
        if (v1ok) {
            int t1 = s_ct[rs1];
            r1 = reinterpret_cast<const float4*>(rep + ((size_t)t1 * B_DIM + b) * D_DIM);
        }
        float4 a0 = z, a1 = z, a2 = z, a3 = z;
        float4 b0 = z, b1 = z, b2 = z, b3 = z;
        if (v0ok) { a0 = r0[lane]; a1 = r0[lane + 32]; a2 = r0[lane + 64]; a3 = r0[lane + 96]; }
        if (v1ok) { b0 = r1[lane]; b1 = r1[lane + 32]; b2 = r1[lane + 64]; b3 = r1[lane + 96]; }
        o0[lane]      = a0; o0[lane + 32] = a1; o0[lane + 64] = a2; o0[lane + 96] = a3;
        o1[lane]      = b0; o1[lane + 32] = b1; o1[lane + 64] = b2; o1[lane + 96] = b3;
        return;
    }

    // General path: per-row averaging loop.
    #pragma unroll
    for (int r = 0; r < 2; r++) {
        bool valid = r ? v1ok : v0ok;
        int rs = r ? rs1 : rs0;
        int cnt = r ? cc1 : cc0;
        float4* orow = r ? o1 : o0;
        if (!valid) {
            orow[lane] = z; orow[lane + 32] = z; orow[lane + 64] = z; orow[lane + 96] = z;
            continue;
        }
        float4 acc0 = z, acc1 = z, acc2 = z, acc3 = z;
        for (int k = 0; k < cnt; k++) {
            int t = s_ct[rs + k];
            const float4* rrow =
                reinterpret_cast<const float4*>(rep + ((size_t)t * B_DIM + b) * D_DIM);
            float4 q0 = rrow[lane];
            float4 q1 = rrow[lane + 32];
            float4 q2 = rrow[lane + 64];
            float4 q3 = rrow[lane + 96];
            acc0.x += q0.x; acc0.y += q0.y; acc0.z += q0.z; acc0.w += q0.w;
            acc1.x += q1.x; acc1.y += q1.y; acc1.z += q1.z; acc1.w += q1.w;
            acc2.x += q2.x; acc2.y += q2.y; acc2.z += q2.z; acc2.w += q2.w;
            acc3.x += q3.x; acc3.y += q3.y; acc3.z += q3.z; acc3.w += q3.w;
        }
        float inv = 1.0f / (float)cnt;
        acc0.x *= inv; acc0.y *= inv; acc0.z *= inv; acc0.w *= inv;
        acc1.x *= inv; acc1.y *= inv; acc1.z *= inv; acc1.w *= inv;
        acc2.x *= inv; acc2.y *= inv; acc2.z *= inv; acc2.w *= inv;
        acc3.x *= inv; acc3.y *= inv; acc3.z *= inv; acc3.w *= inv;
        orow[lane]      = acc0;
        orow[lane + 32] = acc1;
        orow[lane + 64] = acc2;
        orow[lane + 96] = acc3;
    }
}

extern "C" void kernel_launch(void* const* d_in, const int* in_sizes, int n_in,
                              void* d_out, int out_size) {
    const float* rep = (const float*)d_in[0];          // [T,B,D] f32
    const float* logit = (const float*)d_in[1];        // [T,B,C] f32
    const unsigned char* padding = (const unsigned char*)d_in[2];  // [B,T] bool
    float* out = (float*)d_out;

    // K1: 32768 rows, warp per row, 8 rows per 256-thread block
    argmax_kernel<<<(T_DIM * B_DIM) / 8, 256>>>(logit, padding);

    // K23: fused RLE + gather. Grid (64, B), 256 threads.
    dim3 grid(T_DIM / 2 / 8, B_DIM);
    fused_rle_gather<<<grid, 256>>>(rep, out);
}